// round 2
// baseline (speedup 1.0000x reference)
#include <cuda_runtime.h>
#include <math.h>

// Problem constants (from reference): N=4096, D=256, TEMP=1.0
#define DIMS 256

// Global scratch accumulators (no device allocation allowed).
__device__ float g_acc[2];

__global__ void zero_acc_kernel() {
    if (threadIdx.x < 2) g_acc[threadIdx.x] = 0.0f;
}

__device__ __forceinline__ float softplus_stable(float z) {
    // log(1 + e^z), stable for large |z|
    return (z > 0.0f) ? (z + log1pf(expf(-z))) : log1pf(expf(z));
}

// One warp per pair; each warp walks a CONTIGUOUS chunk of the pair list so
// that consecutive pos pairs (which share row i) hit in L1.
__global__ void __launch_bounds__(256)
pair_loss_kernel(const float* __restrict__ X,
                 const float* __restrict__ bias,
                 const int*   __restrict__ pos_idx,
                 const int*   __restrict__ neg_idx,
                 int P)
{
    const int lane    = threadIdx.x & 31;
    const int warp_id = (blockIdx.x * blockDim.x + threadIdx.x) >> 5;
    const int nwarps  = (gridDim.x * blockDim.x) >> 5;

    const int total = 2 * P;
    // contiguous chunk per warp
    const int chunk = (total + nwarps - 1) / nwarps;
    int p_begin = warp_id * chunk;
    int p_end   = p_begin + chunk;
    if (p_end > total) p_end = total;

    const float b = bias[0];

    float acc_pos = 0.0f;
    float acc_neg = 0.0f;

    for (int p = p_begin; p < p_end; ++p) {
        const bool is_pos = (p < P);
        const int  q      = is_pos ? p : (p - P);
        const int* idx    = is_pos ? pos_idx : neg_idx;

        const int i = idx[2 * q];
        const int j = idx[2 * q + 1];

        const float4* ri = (const float4*)(X + (size_t)i * DIMS);
        const float4* rj = (const float4*)(X + (size_t)j * DIMS);

        // 256 floats = 64 float4; 32 lanes x 2 float4 each
        float4 a0 = ri[lane];
        float4 c0 = rj[lane];
        float4 a1 = ri[lane + 32];
        float4 c1 = rj[lane + 32];

        float d0 = a0.x - c0.x, d1 = a0.y - c0.y, d2 = a0.z - c0.z, d3 = a0.w - c0.w;
        float d4 = a1.x - c1.x, d5 = a1.y - c1.y, d6 = a1.z - c1.z, d7 = a1.w - c1.w;

        float s = d0 * d0;
        s = fmaf(d1, d1, s);
        s = fmaf(d2, d2, s);
        s = fmaf(d3, d3, s);
        s = fmaf(d4, d4, s);
        s = fmaf(d5, d5, s);
        s = fmaf(d6, d6, s);
        s = fmaf(d7, d7, s);

        // warp tree-reduce squared distance
        #pragma unroll
        for (int off = 16; off > 0; off >>= 1)
            s += __shfl_xor_sync(0xFFFFFFFFu, s, off);

        if (lane == 0) {
            // pos: softplus(-(b - d)) = softplus(d - b)
            // neg: softplus(  b - d )
            float z  = is_pos ? (s - b) : (b - s);
            float sp = softplus_stable(z);
            if (is_pos) acc_pos += sp;
            else        acc_neg += sp;
        }
    }

    if (lane == 0) {
        if (acc_pos != 0.0f) atomicAdd(&g_acc[0], acc_pos);
        if (acc_neg != 0.0f) atomicAdd(&g_acc[1], acc_neg);
    }
}

__global__ void finalize_kernel(float* __restrict__ out, float inv_P) {
    if (threadIdx.x < 2) out[threadIdx.x] = g_acc[threadIdx.x] * inv_P;
}

extern "C" void kernel_launch(void* const* d_in, const int* in_sizes, int n_in,
                              void* d_out, int out_size)
{
    const float* X       = (const float*)d_in[0];   // [N, 256] fp32
    const float* bias    = (const float*)d_in[1];   // [1]
    const int*   pos_idx = (const int*)d_in[2];     // [P, 2]
    const int*   neg_idx = (const int*)d_in[3];     // [P, 2]
    float*       out     = (float*)d_out;           // [2]

    const int P = in_sizes[2] / 2;

    zero_acc_kernel<<<1, 32>>>();

    // 148 SMs x 8 blocks of 256 threads = one full wave at 2048 thr/SM
    const int threads = 256;
    const int blocks  = 148 * 8;
    pair_loss_kernel<<<blocks, threads>>>(X, bias, pos_idx, neg_idx, P);

    finalize_kernel<<<1, 32>>>(out, 1.0f / (float)P);
}

// round 3
// speedup vs baseline: 1.0375x; 1.0375x over previous
#include <cuda_runtime.h>
#include <cuda_fp16.h>
#include <math.h>

#define DIMS 256
#define NROWS 4096

// Global scratch (no device allocation allowed).
__device__ float  g_acc[2];
__device__ __half g_Xh[NROWS * DIMS];   // 2 MB fp16 copy of Xemb

__global__ void zero_acc_kernel() {
    if (threadIdx.x < 2) g_acc[threadIdx.x] = 0.0f;
}

// Convert Xemb (fp32) -> g_Xh (fp16). 1M floats, 4 per thread.
__global__ void __launch_bounds__(256)
convert_kernel(const float* __restrict__ X) {
    int idx = blockIdx.x * blockDim.x + threadIdx.x;   // one float4 per thread
    float4 v = ((const float4*)X)[idx];
    __half2* out = (__half2*)g_Xh;
    out[2 * idx]     = __floats2half2_rn(v.x, v.y);
    out[2 * idx + 1] = __floats2half2_rn(v.z, v.w);
}

__device__ __forceinline__ float softplus_stable(float z) {
    return (z > 0.0f) ? (z + log1pf(expf(-z))) : log1pf(expf(z));
}

// Warp computes squared distance for pair (i, j) from the fp16 table.
// Row = 256 halves = 512 B = 32 lanes x 16 B.
__device__ __forceinline__ float pair_sqdist_w(int i, int j, int lane) {
    const float4* ri = (const float4*)(g_Xh + (size_t)i * DIMS);
    const float4* rj = (const float4*)(g_Xh + (size_t)j * DIMS);
    float4 a = ri[lane];
    float4 c = rj[lane];

    const __half2* ha = (const __half2*)&a;
    const __half2* hc = (const __half2*)&c;

    float s = 0.0f;
    #pragma unroll
    for (int k = 0; k < 4; ++k) {
        float2 fa = __half22float2(ha[k]);
        float2 fc = __half22float2(hc[k]);
        float d0 = fa.x - fc.x;
        float d1 = fa.y - fc.y;
        s = fmaf(d0, d0, s);
        s = fmaf(d1, d1, s);
    }
    #pragma unroll
    for (int off = 16; off > 0; off >>= 1)
        s += __shfl_xor_sync(0xFFFFFFFFu, s, off);
    return s;
}

// Each warp takes one contiguous chunk of pos pairs (L1 reuse: cluster rows)
// AND one contiguous chunk of neg pairs (balances L2-bound work).
__global__ void __launch_bounds__(256)
pair_loss_kernel(const float* __restrict__ bias,
                 const int*   __restrict__ pos_idx,
                 const int*   __restrict__ neg_idx,
                 int P)
{
    const int lane    = threadIdx.x & 31;
    const int warp_id = (blockIdx.x * blockDim.x + threadIdx.x) >> 5;
    const int nwarps  = (gridDim.x * blockDim.x) >> 5;

    const int chunk = (P + nwarps - 1) / nwarps;
    int p0 = warp_id * chunk;
    int p1 = p0 + chunk; if (p1 > P) p1 = P;

    const float b = bias[0];

    float acc_pos = 0.0f;
    for (int p = p0; p < p1; ++p) {
        int i = pos_idx[2 * p];
        int j = pos_idx[2 * p + 1];
        float s = pair_sqdist_w(i, j, lane);
        if (lane == 0) acc_pos += softplus_stable(s - b);   // softplus(-(b-d)) = softplus(d-b)
    }

    float acc_neg = 0.0f;
    for (int p = p0; p < p1; ++p) {
        int i = neg_idx[2 * p];
        int j = neg_idx[2 * p + 1];
        float s = pair_sqdist_w(i, j, lane);
        if (lane == 0) acc_neg += softplus_stable(b - s);
    }

    if (lane == 0) {
        if (acc_pos != 0.0f) atomicAdd(&g_acc[0], acc_pos);
        if (acc_neg != 0.0f) atomicAdd(&g_acc[1], acc_neg);
    }
}

__global__ void finalize_kernel(float* __restrict__ out, float inv_P) {
    if (threadIdx.x < 2) out[threadIdx.x] = g_acc[threadIdx.x] * inv_P;
}

extern "C" void kernel_launch(void* const* d_in, const int* in_sizes, int n_in,
                              void* d_out, int out_size)
{
    const float* X       = (const float*)d_in[0];   // [4096, 256] fp32
    const float* bias    = (const float*)d_in[1];   // [1]
    const int*   pos_idx = (const int*)d_in[2];     // [P, 2]
    const int*   neg_idx = (const int*)d_in[3];     // [P, 2]
    float*       out     = (float*)d_out;           // [2]

    const int P = in_sizes[2] / 2;

    zero_acc_kernel<<<1, 32>>>();

    // 4096*256 floats / 4 per thread / 256 threads = 1024 blocks
    convert_kernel<<<(NROWS * DIMS / 4) / 256, 256>>>(X);

    const int threads = 256;
    const int blocks  = 148 * 8;
    pair_loss_kernel<<<blocks, threads>>>(bias, pos_idx, neg_idx, P);

    finalize_kernel<<<1, 32>>>(out, 1.0f / (float)P);
}